// round 10
// baseline (speedup 1.0000x reference)
#include <cuda_runtime.h>
#include <cuda_fp16.h>
#include <math.h>
#include <stdint.h>

#define N_NODES 50000
#define N_EDGES 800000
#define D_IN    256
#define D_HID   128
#define D_ENC   64
#define MAXDEG  96
#define GEMM_BLOCKS ((N_NODES + 127) / 128)          // 391
#define DINV_BLOCKS 25                               // 25*256*8 >= 50000

// ---------------- scratch (static device globals; no allocations) ----------
__device__ int    d_counts[N_NODES];
__device__ float  d_dinv[N_NODES];
__device__ int    d_ell[(size_t)N_NODES * MAXDEG];   // padded adjacency (src ids)
__device__ __half d_g[(size_t)N_NODES * D_HID];      // dinv[r] * (x @ W1)[r]  (fp16)
__device__ float  d_td[N_NODES];                     // dinv[i] * (h1 . v)
__device__ float  d_v[D_HID];                        // W2 @ Wfc
__device__ float  d_s;                               // b2 . Wfc + bfc
__device__ float  d_W1t[D_HID * D_IN];               // W1 transposed [n][k]

__device__ __forceinline__ int clamp_node(int v) {
    return (v >= 0 && v < N_NODES) ? v : 0;
}

__device__ __forceinline__ float to_tf32(float x) {
    float r;
    asm("cvt.rna.tf32.f32 %0, %1;" : "=f"(r) : "f"(x));
    return r;
}

// ---------------- single-pass ELL build (count + place) ---------------------
__global__ void fill_ell_kernel(const int* __restrict__ row,
                                const int* __restrict__ col) {
    int e = (blockIdx.x * blockDim.x + threadIdx.x) * 4;
    if (e + 3 < N_EDGES) {
        int4 c = *reinterpret_cast<const int4*>(col + e);
        int4 r = *reinterpret_cast<const int4*>(row + e);
        int c0 = clamp_node(c.x), c1 = clamp_node(c.y);
        int c2 = clamp_node(c.z), c3 = clamp_node(c.w);
        int p0 = atomicAdd(&d_counts[c0], 1);
        int p1 = atomicAdd(&d_counts[c1], 1);
        int p2 = atomicAdd(&d_counts[c2], 1);
        int p3 = atomicAdd(&d_counts[c3], 1);
        if (p0 < MAXDEG) d_ell[(size_t)c0 * MAXDEG + p0] = clamp_node(r.x);
        if (p1 < MAXDEG) d_ell[(size_t)c1 * MAXDEG + p1] = clamp_node(r.y);
        if (p2 < MAXDEG) d_ell[(size_t)c2 * MAXDEG + p2] = clamp_node(r.z);
        if (p3 < MAXDEG) d_ell[(size_t)c3 * MAXDEG + p3] = clamp_node(r.w);
    } else {
        for (int k = e; k < N_EDGES; k++) {
            int cc = clamp_node(col[k]);
            int p = atomicAdd(&d_counts[cc], 1);
            if (p < MAXDEG) d_ell[(size_t)cc * MAXDEG + p] = clamp_node(row[k]);
        }
    }
}

// ---------------- weight prep: transpose W1 (32 blocks) + v,s (1 block) -----
__global__ void prep_weights_kernel(const float* __restrict__ W1,
                                    const float* __restrict__ W2,
                                    const float* __restrict__ b2,
                                    const float* __restrict__ Wfc,
                                    const float* __restrict__ bfc) {
    if (blockIdx.x < 32) {
        __shared__ float tt[32][33];
        int b = blockIdx.x;
        int bx = b & 7;              // k tile (8)
        int by = b >> 3;             // n tile (4)
        int x0 = bx * 32, y0 = by * 32;
        int tx = threadIdx.x & 31, ty = threadIdx.x >> 5;  // 32 x 8
        #pragma unroll
        for (int i = 0; i < 32; i += 8)
            tt[ty + i][tx] = W1[(size_t)(x0 + ty + i) * D_HID + y0 + tx];
        __syncthreads();
        #pragma unroll
        for (int i = 0; i < 32; i += 8)
            d_W1t[(size_t)(y0 + ty + i) * D_IN + x0 + tx] = tt[tx][ty + i];
    } else {
        __shared__ float red[D_ENC];
        int j = threadIdx.x;
        if (j < D_HID) {
            float acc = 0.f;
            #pragma unroll 8
            for (int k = 0; k < D_ENC; k++)
                acc = fmaf(W2[j * D_ENC + k], Wfc[k], acc);
            d_v[j] = acc;
        }
        if (j < D_ENC) red[j] = b2[j] * Wfc[j];
        __syncthreads();
        if (j == 0) {
            float s = bfc[0];
            for (int k = 0; k < D_ENC; k++) s += red[k];
            d_s = s;
        }
    }
}

// ---------------- GEMM1 (tf32 mma); epilogue scales by dinv -> fp16 ---------
__global__ __launch_bounds__(256) void gemm1_mma_kernel(const float* __restrict__ x) {
    if (blockIdx.x >= GEMM_BLOCKS) {
        int base = ((blockIdx.x - GEMM_BLOCKS) * 256 + threadIdx.x) * 8;
        #pragma unroll
        for (int i = 0; i < 8; i++) {
            int idx = base + i;
            if (idx < N_NODES)
                d_dinv[idx] = rsqrtf((float)(d_counts[idx] + 1));  // deg = cnt+1
        }
        return;
    }

    __shared__ float As[128][36];
    __shared__ float Bt[128][36];

    int tid  = threadIdx.x;
    int warp = tid >> 5;
    int lane = tid & 31;
    int g  = lane >> 2;
    int tg = lane & 3;
    int rowBase = blockIdx.x * 128;

    float acc[16][4];
    #pragma unroll
    for (int nt = 0; nt < 16; nt++)
        #pragma unroll
        for (int i = 0; i < 4; i++) acc[nt][i] = 0.f;

    int lr = tid >> 1;
    int cb = (tid & 1) * 16;
    int gr = rowBase + lr;
    bool valid = gr < N_NODES;
    const float4* pA = reinterpret_cast<const float4*>(
        x + (size_t)(valid ? gr : 0) * D_IN + cb);
    const float4* pB = reinterpret_cast<const float4*>(
        d_W1t + (size_t)lr * D_IN + cb);

    float4 ra[4], rb[4];
    #pragma unroll
    for (int i = 0; i < 4; i++) {
        ra[i] = valid ? pA[i] : make_float4(0.f, 0.f, 0.f, 0.f);
        rb[i] = pB[i];
    }
    #pragma unroll
    for (int i = 0; i < 4; i++) {
        As[lr][cb + i * 4 + 0] = to_tf32(ra[i].x);
        As[lr][cb + i * 4 + 1] = to_tf32(ra[i].y);
        As[lr][cb + i * 4 + 2] = to_tf32(ra[i].z);
        As[lr][cb + i * 4 + 3] = to_tf32(ra[i].w);
        Bt[lr][cb + i * 4 + 0] = to_tf32(rb[i].x);
        Bt[lr][cb + i * 4 + 1] = to_tf32(rb[i].y);
        Bt[lr][cb + i * 4 + 2] = to_tf32(rb[i].z);
        Bt[lr][cb + i * 4 + 3] = to_tf32(rb[i].w);
    }
    __syncthreads();

    #pragma unroll
    for (int c = 0; c < 8; c++) {
        if (c < 7) {
            #pragma unroll
            for (int i = 0; i < 4; i++) {
                ra[i] = valid ? pA[(c + 1) * 8 + i] : make_float4(0.f, 0.f, 0.f, 0.f);
                rb[i] = pB[(c + 1) * 8 + i];
            }
        }
        #pragma unroll
        for (int k8 = 0; k8 < 4; k8++) {
            int kk = k8 * 8;
            uint32_t a0 = __float_as_uint(As[warp * 16 + g    ][kk + tg    ]);
            uint32_t a1 = __float_as_uint(As[warp * 16 + g + 8][kk + tg    ]);
            uint32_t a2 = __float_as_uint(As[warp * 16 + g    ][kk + tg + 4]);
            uint32_t a3 = __float_as_uint(As[warp * 16 + g + 8][kk + tg + 4]);
            #pragma unroll
            for (int nt = 0; nt < 16; nt++) {
                uint32_t b0 = __float_as_uint(Bt[nt * 8 + g][kk + tg    ]);
                uint32_t b1 = __float_as_uint(Bt[nt * 8 + g][kk + tg + 4]);
                asm volatile(
                    "mma.sync.aligned.m16n8k8.row.col.f32.tf32.tf32.f32 "
                    "{%0,%1,%2,%3}, {%4,%5,%6,%7}, {%8,%9}, {%0,%1,%2,%3};"
                    : "+f"(acc[nt][0]), "+f"(acc[nt][1]),
                      "+f"(acc[nt][2]), "+f"(acc[nt][3])
                    : "r"(a0), "r"(a1), "r"(a2), "r"(a3), "r"(b0), "r"(b1));
            }
        }
        if (c < 7) {
            __syncthreads();
            #pragma unroll
            for (int i = 0; i < 4; i++) {
                As[lr][cb + i * 4 + 0] = to_tf32(ra[i].x);
                As[lr][cb + i * 4 + 1] = to_tf32(ra[i].y);
                As[lr][cb + i * 4 + 2] = to_tf32(ra[i].z);
                As[lr][cb + i * 4 + 3] = to_tf32(ra[i].w);
                Bt[lr][cb + i * 4 + 0] = to_tf32(rb[i].x);
                Bt[lr][cb + i * 4 + 1] = to_tf32(rb[i].y);
                Bt[lr][cb + i * 4 + 2] = to_tf32(rb[i].z);
                Bt[lr][cb + i * 4 + 3] = to_tf32(rb[i].w);
            }
            __syncthreads();
        }
    }

    int r0 = rowBase + warp * 16 + g;
    int r1 = r0 + 8;
    float di0 = (r0 < N_NODES) ? rsqrtf((float)(d_counts[r0] + 1)) : 0.f;
    float di1 = (r1 < N_NODES) ? rsqrtf((float)(d_counts[r1] + 1)) : 0.f;
    __half2* g2 = reinterpret_cast<__half2*>(d_g);
    #pragma unroll
    for (int nt = 0; nt < 16; nt++) {
        int h = nt * 4 + tg;
        if (r0 < N_NODES)
            g2[(size_t)r0 * 64 + h] =
                __floats2half2_rn(di0 * acc[nt][0], di0 * acc[nt][1]);
        if (r1 < N_NODES)
            g2[(size_t)r1 * 64 + h] =
                __floats2half2_rn(di1 * acc[nt][2], di1 * acc[nt][3]);
    }
}

// ---------------- layer-1 aggregation: 2 nodes/warp, 16 lanes/node ----------
// lane owns 8 features (uint4 = 8 halves); pure sum of pre-scaled rows
__global__ __launch_bounds__(256) void agg1_kernel(const float* __restrict__ b1) {
    int wid  = (blockIdx.x * blockDim.x + threadIdx.x) >> 5;  // warp id
    int half = (threadIdx.x >> 4) & 1;
    int sl   = threadIdx.x & 15;          // sub-lane within node
    int node = wid * 2 + half;
    if (node >= N_NODES) return;
    int cnt = d_counts[node];
    if (cnt > MAXDEG) cnt = MAXDEG;
    const int* adj = d_ell + (size_t)node * MAXDEG;
    float di = d_dinv[node];
    const uint4* g16 = reinterpret_cast<const uint4*>(d_g);  // 16 uint4 per row

    float acc[8];
    #pragma unroll
    for (int i = 0; i < 8; i++) acc[i] = 0.f;

    int j = 0;
    for (; j + 2 <= cnt; j += 2) {
        int s0 = adj[j];
        int s1 = adj[j + 1];
        uint4 u0 = g16[(size_t)s0 * 16 + sl];
        uint4 u1 = g16[(size_t)s1 * 16 + sl];
        float2 p0 = __half22float2(*reinterpret_cast<__half2*>(&u0.x));
        float2 p1 = __half22float2(*reinterpret_cast<__half2*>(&u0.y));
        float2 p2 = __half22float2(*reinterpret_cast<__half2*>(&u0.z));
        float2 p3 = __half22float2(*reinterpret_cast<__half2*>(&u0.w));
        float2 q0 = __half22float2(*reinterpret_cast<__half2*>(&u1.x));
        float2 q1 = __half22float2(*reinterpret_cast<__half2*>(&u1.y));
        float2 q2 = __half22float2(*reinterpret_cast<__half2*>(&u1.z));
        float2 q3 = __half22float2(*reinterpret_cast<__half2*>(&u1.w));
        acc[0] += p0.x + q0.x; acc[1] += p0.y + q0.y;
        acc[2] += p1.x + q1.x; acc[3] += p1.y + q1.y;
        acc[4] += p2.x + q2.x; acc[5] += p2.y + q2.y;
        acc[6] += p3.x + q3.x; acc[7] += p3.y + q3.y;
    }
    // remainder edge (if cnt odd) and self loop
    #pragma unroll
    for (int t = 0; t < 2; t++) {
        int s0;
        if (t == 0) { if (j >= cnt) continue; s0 = adj[j]; }
        else         s0 = node;                      // self loop (pre-scaled)
        uint4 u0 = g16[(size_t)s0 * 16 + sl];
        float2 p0 = __half22float2(*reinterpret_cast<__half2*>(&u0.x));
        float2 p1 = __half22float2(*reinterpret_cast<__half2*>(&u0.y));
        float2 p2 = __half22float2(*reinterpret_cast<__half2*>(&u0.z));
        float2 p3 = __half22float2(*reinterpret_cast<__half2*>(&u0.w));
        acc[0] += p0.x; acc[1] += p0.y;
        acc[2] += p1.x; acc[3] += p1.y;
        acc[4] += p2.x; acc[5] += p2.y;
        acc[6] += p3.x; acc[7] += p3.y;
    }

    const float4* b4 = reinterpret_cast<const float4*>(b1);
    const float4* v4 = reinterpret_cast<const float4*>(d_v);
    float4 bb0 = b4[sl * 2], bb1 = b4[sl * 2 + 1];
    float4 vv0 = v4[sl * 2], vv1 = v4[sl * 2 + 1];
    float p = 0.f;
    p += fmaxf(fmaf(acc[0], di, bb0.x), 0.f) * vv0.x;
    p += fmaxf(fmaf(acc[1], di, bb0.y), 0.f) * vv0.y;
    p += fmaxf(fmaf(acc[2], di, bb0.z), 0.f) * vv0.z;
    p += fmaxf(fmaf(acc[3], di, bb0.w), 0.f) * vv0.w;
    p += fmaxf(fmaf(acc[4], di, bb1.x), 0.f) * vv1.x;
    p += fmaxf(fmaf(acc[5], di, bb1.y), 0.f) * vv1.y;
    p += fmaxf(fmaf(acc[6], di, bb1.z), 0.f) * vv1.z;
    p += fmaxf(fmaf(acc[7], di, bb1.w), 0.f) * vv1.w;
    #pragma unroll
    for (int off = 8; off > 0; off >>= 1)
        p += __shfl_down_sync(0xFFFFFFFFu, p, off, 16);
    if (sl == 0) d_td[node] = di * p;
}

// ---------------- layer-2 (collapsed, scalar) + sigmoid ---------------------
__global__ void agg2_kernel(float* __restrict__ out) {
    int i = blockIdx.x * blockDim.x + threadIdx.x;
    if (i >= N_NODES) return;
    int cnt = d_counts[i];
    if (cnt > MAXDEG) cnt = MAXDEG;
    const int* adj = d_ell + (size_t)i * MAXDEG;
    float acc = 0.f;
    int j = 0;
    for (; j + 4 <= cnt; j += 4) {
        int s0 = adj[j + 0];
        int s1 = adj[j + 1];
        int s2 = adj[j + 2];
        int s3 = adj[j + 3];
        acc += d_td[s0] + d_td[s1] + d_td[s2] + d_td[s3];
    }
    for (; j < cnt; j++) acc += d_td[adj[j]];
    float di = d_dinv[i];
    float u = di * (acc + d_td[i]) + d_s;
    out[i] = 1.f / (1.f + expf(-u));
}

// ---------------- launcher ---------------------------------------------------
extern "C" void kernel_launch(void* const* d_in, const int* in_sizes, int n_in,
                              void* d_out, int out_size) {
    const float* x   = (const float*)d_in[0];
    const int*   ei  = (const int*)d_in[1];
    const float* W1  = (const float*)d_in[2];
    const float* b1  = (const float*)d_in[3];
    const float* W2  = (const float*)d_in[4];
    const float* b2  = (const float*)d_in[5];
    const float* Wfc = (const float*)d_in[6];
    const float* bfc = (const float*)d_in[7];
    float* out = (float*)d_out;

    const int* row = ei;            // sources
    const int* col = ei + N_EDGES;  // targets

    void* counts_ptr = nullptr;
    cudaGetSymbolAddress(&counts_ptr, d_counts);
    cudaMemsetAsync(counts_ptr, 0, N_NODES * sizeof(int));

    prep_weights_kernel<<<33, 256>>>(W1, W2, b2, Wfc, bfc);
    fill_ell_kernel<<<(N_EDGES / 4 + 255) / 256, 256>>>(row, col);
    gemm1_mma_kernel<<<GEMM_BLOCKS + DINV_BLOCKS, 256>>>(x);
    agg1_kernel<<<(N_NODES / 16), 256>>>(b1);   // 2 nodes per warp, 16 per block
    agg2_kernel<<<(N_NODES + 255) / 256, 256>>>(out);
}

// round 11
// speedup vs baseline: 1.1441x; 1.1441x over previous
#include <cuda_runtime.h>
#include <cuda_fp16.h>
#include <math.h>
#include <stdint.h>

#define N_NODES 50000
#define N_EDGES 800000
#define D_IN    256
#define D_HID   128
#define D_ENC   64
#define MAXDEG  96
#define GEMM_BLOCKS ((N_NODES + 127) / 128)          // 391
#define DINV_BLOCKS 25                               // 25*256*8 >= 50000

// ---------------- scratch (static device globals; no allocations) ----------
__device__ int    d_counts[N_NODES];
__device__ float  d_dinv[N_NODES];
__device__ int    d_ell[(size_t)N_NODES * MAXDEG];   // padded adjacency (src ids)
__device__ __half d_g[(size_t)N_NODES * D_HID];      // dinv[r] * (x @ W1)[r]  (fp16)
__device__ float  d_td[N_NODES];                     // dinv[i] * (h1 . v)
__device__ float  d_v[D_HID];                        // W2 @ Wfc
__device__ float  d_s;                               // b2 . Wfc + bfc
__device__ float  d_W1t[D_HID * D_IN];               // W1 transposed [n][k]

__device__ __forceinline__ int clamp_node(int v) {
    return (v >= 0 && v < N_NODES) ? v : 0;
}

// pack two f32 -> bf16x2 (lo = first arg, hi = second)
__device__ __forceinline__ uint32_t pack_bf16(float lo, float hi) {
    uint32_t r;
    asm("cvt.rn.bf16x2.f32 %0, %1, %2;" : "=r"(r) : "f"(hi), "f"(lo));
    return r;
}

// ---------------- single-pass ELL build (count + place) ---------------------
__global__ void fill_ell_kernel(const int* __restrict__ row,
                                const int* __restrict__ col) {
    int e = (blockIdx.x * blockDim.x + threadIdx.x) * 4;
    if (e + 3 < N_EDGES) {
        int4 c = *reinterpret_cast<const int4*>(col + e);
        int4 r = *reinterpret_cast<const int4*>(row + e);
        int c0 = clamp_node(c.x), c1 = clamp_node(c.y);
        int c2 = clamp_node(c.z), c3 = clamp_node(c.w);
        int p0 = atomicAdd(&d_counts[c0], 1);
        int p1 = atomicAdd(&d_counts[c1], 1);
        int p2 = atomicAdd(&d_counts[c2], 1);
        int p3 = atomicAdd(&d_counts[c3], 1);
        if (p0 < MAXDEG) d_ell[(size_t)c0 * MAXDEG + p0] = clamp_node(r.x);
        if (p1 < MAXDEG) d_ell[(size_t)c1 * MAXDEG + p1] = clamp_node(r.y);
        if (p2 < MAXDEG) d_ell[(size_t)c2 * MAXDEG + p2] = clamp_node(r.z);
        if (p3 < MAXDEG) d_ell[(size_t)c3 * MAXDEG + p3] = clamp_node(r.w);
    } else {
        for (int k = e; k < N_EDGES; k++) {
            int cc = clamp_node(col[k]);
            int p = atomicAdd(&d_counts[cc], 1);
            if (p < MAXDEG) d_ell[(size_t)cc * MAXDEG + p] = clamp_node(row[k]);
        }
    }
}

// ---------------- weight prep: transpose W1 (32 blocks) + v,s (1 block) -----
__global__ void prep_weights_kernel(const float* __restrict__ W1,
                                    const float* __restrict__ W2,
                                    const float* __restrict__ b2,
                                    const float* __restrict__ Wfc,
                                    const float* __restrict__ bfc) {
    if (blockIdx.x < 32) {
        __shared__ float tt[32][33];
        int b = blockIdx.x;
        int bx = b & 7;              // k tile (8)
        int by = b >> 3;             // n tile (4)
        int x0 = bx * 32, y0 = by * 32;
        int tx = threadIdx.x & 31, ty = threadIdx.x >> 5;  // 32 x 8
        #pragma unroll
        for (int i = 0; i < 32; i += 8)
            tt[ty + i][tx] = W1[(size_t)(x0 + ty + i) * D_HID + y0 + tx];
        __syncthreads();
        #pragma unroll
        for (int i = 0; i < 32; i += 8)
            d_W1t[(size_t)(y0 + ty + i) * D_IN + x0 + tx] = tt[tx][ty + i];
    } else {
        __shared__ float red[D_ENC];
        int j = threadIdx.x;
        if (j < D_HID) {
            float acc = 0.f;
            #pragma unroll 8
            for (int k = 0; k < D_ENC; k++)
                acc = fmaf(W2[j * D_ENC + k], Wfc[k], acc);
            d_v[j] = acc;
        }
        if (j < D_ENC) red[j] = b2[j] * Wfc[j];
        __syncthreads();
        if (j == 0) {
            float s = bfc[0];
            for (int k = 0; k < D_ENC; k++) s += red[k];
            d_s = s;
        }
    }
}

// ---------------- GEMM1 (bf16 m16n8k16 mma); epilogue scales by dinv -> fp16
// smem rows hold one 32-K chunk as 16 used uint32 (bf16x2), stride 20 u32
__global__ __launch_bounds__(256) void gemm1_mma_kernel(const float* __restrict__ x) {
    if (blockIdx.x >= GEMM_BLOCKS) {
        int base = ((blockIdx.x - GEMM_BLOCKS) * 256 + threadIdx.x) * 8;
        #pragma unroll
        for (int i = 0; i < 8; i++) {
            int idx = base + i;
            if (idx < N_NODES)
                d_dinv[idx] = rsqrtf((float)(d_counts[idx] + 1));  // deg = cnt+1
        }
        return;
    }

    __shared__ uint32_t As[128][20];   // bf16x2, 16 used + 4 pad (bank-clean)
    __shared__ uint32_t Bs[128][20];

    int tid  = threadIdx.x;
    int warp = tid >> 5;
    int lane = tid & 31;
    int g  = lane >> 2;
    int tg = lane & 3;
    int rowBase = blockIdx.x * 128;

    float acc[16][4];
    #pragma unroll
    for (int nt = 0; nt < 16; nt++)
        #pragma unroll
        for (int i = 0; i < 4; i++) acc[nt][i] = 0.f;

    int lr = tid >> 1;            // smem row this thread fills
    int h  = tid & 1;             // which 16-float half of the 32-K chunk
    int gr = rowBase + lr;
    bool valid = gr < N_NODES;
    const float4* pA = reinterpret_cast<const float4*>(
        x + (size_t)(valid ? gr : 0) * D_IN + h * 16);
    const float4* pB = reinterpret_cast<const float4*>(
        d_W1t + (size_t)lr * D_IN + h * 16);

    // K-chunk c occupies float4 indices [8c, 8c+3] from each thread's base.
    float4 ra[4], rb[4];
    #pragma unroll
    for (int i = 0; i < 4; i++) {
        ra[i] = valid ? pA[i] : make_float4(0.f, 0.f, 0.f, 0.f);
        rb[i] = pB[i];
    }
    #pragma unroll
    for (int i = 0; i < 4; i++) {
        As[lr][h * 8 + i * 2    ] = pack_bf16(ra[i].x, ra[i].y);
        As[lr][h * 8 + i * 2 + 1] = pack_bf16(ra[i].z, ra[i].w);
        Bs[lr][h * 8 + i * 2    ] = pack_bf16(rb[i].x, rb[i].y);
        Bs[lr][h * 8 + i * 2 + 1] = pack_bf16(rb[i].z, rb[i].w);
    }
    __syncthreads();

    #pragma unroll
    for (int c = 0; c < 8; c++) {
        if (c < 7) {   // prefetch next chunk: float4 index 8*(c+1)+i
            #pragma unroll
            for (int i = 0; i < 4; i++) {
                ra[i] = valid ? pA[(c + 1) * 8 + i] : make_float4(0.f, 0.f, 0.f, 0.f);
                rb[i] = pB[(c + 1) * 8 + i];
            }
        }
        #pragma unroll
        for (int kk = 0; kk < 2; kk++) {   // two k16 steps per 32-K chunk
            uint32_t a0 = As[warp * 16 + g    ][kk * 8 + tg    ];
            uint32_t a1 = As[warp * 16 + g + 8][kk * 8 + tg    ];
            uint32_t a2 = As[warp * 16 + g    ][kk * 8 + 4 + tg];
            uint32_t a3 = As[warp * 16 + g + 8][kk * 8 + 4 + tg];
            #pragma unroll
            for (int nt = 0; nt < 16; nt++) {
                uint32_t b0 = Bs[nt * 8 + g][kk * 8 + tg    ];
                uint32_t b1 = Bs[nt * 8 + g][kk * 8 + 4 + tg];
                asm volatile(
                    "mma.sync.aligned.m16n8k16.row.col.f32.bf16.bf16.f32 "
                    "{%0,%1,%2,%3}, {%4,%5,%6,%7}, {%8,%9}, {%0,%1,%2,%3};"
                    : "+f"(acc[nt][0]), "+f"(acc[nt][1]),
                      "+f"(acc[nt][2]), "+f"(acc[nt][3])
                    : "r"(a0), "r"(a1), "r"(a2), "r"(a3), "r"(b0), "r"(b1));
            }
        }
        if (c < 7) {
            __syncthreads();
            #pragma unroll
            for (int i = 0; i < 4; i++) {
                As[lr][h * 8 + i * 2    ] = pack_bf16(ra[i].x, ra[i].y);
                As[lr][h * 8 + i * 2 + 1] = pack_bf16(ra[i].z, ra[i].w);
                Bs[lr][h * 8 + i * 2    ] = pack_bf16(rb[i].x, rb[i].y);
                Bs[lr][h * 8 + i * 2 + 1] = pack_bf16(rb[i].z, rb[i].w);
            }
            __syncthreads();
        }
    }

    int r0 = rowBase + warp * 16 + g;
    int r1 = r0 + 8;
    float di0 = (r0 < N_NODES) ? rsqrtf((float)(d_counts[r0] + 1)) : 0.f;
    float di1 = (r1 < N_NODES) ? rsqrtf((float)(d_counts[r1] + 1)) : 0.f;
    __half2* g2 = reinterpret_cast<__half2*>(d_g);
    #pragma unroll
    for (int nt = 0; nt < 16; nt++) {
        int hh = nt * 4 + tg;
        if (r0 < N_NODES)
            g2[(size_t)r0 * 64 + hh] =
                __floats2half2_rn(di0 * acc[nt][0], di0 * acc[nt][1]);
        if (r1 < N_NODES)
            g2[(size_t)r1 * 64 + hh] =
                __floats2half2_rn(di1 * acc[nt][2], di1 * acc[nt][3]);
    }
}

// ---------------- layer-1 aggregation: pure sum of pre-scaled rows ----------
// (R9 form: one warp per node, lane owns 4 features as uint2)
__global__ __launch_bounds__(256) void agg1_kernel(const float* __restrict__ b1) {
    int gwarp = (blockIdx.x * blockDim.x + threadIdx.x) >> 5;
    int lane  = threadIdx.x & 31;
    if (gwarp >= N_NODES) return;
    int node  = gwarp;
    int cnt   = d_counts[node];
    if (cnt > MAXDEG) cnt = MAXDEG;
    const int* adj = d_ell + (size_t)node * MAXDEG;
    float di  = d_dinv[node];
    const uint2* g4 = reinterpret_cast<const uint2*>(d_g);

    float4 acc = make_float4(0.f, 0.f, 0.f, 0.f);
    int j = 0;
    for (; j + 4 <= cnt; j += 4) {
        int s0 = adj[j];
        int s1 = adj[j + 1];
        int s2 = adj[j + 2];
        int s3 = adj[j + 3];
        uint2 u0 = g4[(size_t)s0 * 32 + lane];
        uint2 u1 = g4[(size_t)s1 * 32 + lane];
        uint2 u2 = g4[(size_t)s2 * 32 + lane];
        uint2 u3 = g4[(size_t)s3 * 32 + lane];
        float2 a0 = __half22float2(*reinterpret_cast<__half2*>(&u0.x));
        float2 a1 = __half22float2(*reinterpret_cast<__half2*>(&u0.y));
        float2 b0 = __half22float2(*reinterpret_cast<__half2*>(&u1.x));
        float2 b1 = __half22float2(*reinterpret_cast<__half2*>(&u1.y));
        float2 c0 = __half22float2(*reinterpret_cast<__half2*>(&u2.x));
        float2 c1 = __half22float2(*reinterpret_cast<__half2*>(&u2.y));
        float2 e0 = __half22float2(*reinterpret_cast<__half2*>(&u3.x));
        float2 e1 = __half22float2(*reinterpret_cast<__half2*>(&u3.y));
        acc.x += (a0.x + b0.x) + (c0.x + e0.x);
        acc.y += (a0.y + b0.y) + (c0.y + e0.y);
        acc.z += (a1.x + b1.x) + (c1.x + e1.x);
        acc.w += (a1.y + b1.y) + (c1.y + e1.y);
    }
    for (; j < cnt; j++) {
        int s0 = adj[j];
        uint2 u0 = g4[(size_t)s0 * 32 + lane];
        float2 a0 = __half22float2(*reinterpret_cast<__half2*>(&u0.x));
        float2 a1 = __half22float2(*reinterpret_cast<__half2*>(&u0.y));
        acc.x += a0.x; acc.y += a0.y;
        acc.z += a1.x; acc.w += a1.y;
    }
    {   // self loop: g row is pre-scaled by dinv[node]
        uint2 u0 = g4[(size_t)node * 32 + lane];
        float2 a0 = __half22float2(*reinterpret_cast<__half2*>(&u0.x));
        float2 a1 = __half22float2(*reinterpret_cast<__half2*>(&u0.y));
        acc.x += a0.x; acc.y += a0.y;
        acc.z += a1.x; acc.w += a1.y;
    }
    float4 bb = reinterpret_cast<const float4*>(b1)[lane];
    float4 vv = reinterpret_cast<const float4*>(d_v)[lane];
    float h0 = fmaxf(fmaf(acc.x, di, bb.x), 0.f);
    float h1 = fmaxf(fmaf(acc.y, di, bb.y), 0.f);
    float h2 = fmaxf(fmaf(acc.z, di, bb.z), 0.f);
    float h3 = fmaxf(fmaf(acc.w, di, bb.w), 0.f);
    float p = h0 * vv.x + h1 * vv.y + h2 * vv.z + h3 * vv.w;
    #pragma unroll
    for (int off = 16; off > 0; off >>= 1)
        p += __shfl_down_sync(0xFFFFFFFFu, p, off);
    if (lane == 0) d_td[node] = di * p;
}

// ---------------- layer-2 (collapsed, scalar) + sigmoid ---------------------
__global__ void agg2_kernel(float* __restrict__ out) {
    int i = blockIdx.x * blockDim.x + threadIdx.x;
    if (i >= N_NODES) return;
    int cnt = d_counts[i];
    if (cnt > MAXDEG) cnt = MAXDEG;
    const int* adj = d_ell + (size_t)i * MAXDEG;
    float acc = 0.f;
    int j = 0;
    for (; j + 4 <= cnt; j += 4) {
        int s0 = adj[j + 0];
        int s1 = adj[j + 1];
        int s2 = adj[j + 2];
        int s3 = adj[j + 3];
        acc += d_td[s0] + d_td[s1] + d_td[s2] + d_td[s3];
    }
    for (; j < cnt; j++) acc += d_td[adj[j]];
    float di = d_dinv[i];
    float u = di * (acc + d_td[i]) + d_s;
    out[i] = 1.f / (1.f + expf(-u));
}

// ---------------- launcher ---------------------------------------------------
extern "C" void kernel_launch(void* const* d_in, const int* in_sizes, int n_in,
                              void* d_out, int out_size) {
    const float* x   = (const float*)d_in[0];
    const int*   ei  = (const int*)d_in[1];
    const float* W1  = (const float*)d_in[2];
    const float* b1  = (const float*)d_in[3];
    const float* W2  = (const float*)d_in[4];
    const float* b2  = (const float*)d_in[5];
    const float* Wfc = (const float*)d_in[6];
    const float* bfc = (const float*)d_in[7];
    float* out = (float*)d_out;

    const int* row = ei;            // sources
    const int* col = ei + N_EDGES;  // targets

    void* counts_ptr = nullptr;
    cudaGetSymbolAddress(&counts_ptr, d_counts);
    cudaMemsetAsync(counts_ptr, 0, N_NODES * sizeof(int));

    prep_weights_kernel<<<33, 256>>>(W1, W2, b2, Wfc, bfc);
    fill_ell_kernel<<<(N_EDGES / 4 + 255) / 256, 256>>>(row, col);
    gemm1_mma_kernel<<<GEMM_BLOCKS + DINV_BLOCKS, 256>>>(x);
    agg1_kernel<<<(N_NODES + 7) / 8, 256>>>(b1);
    agg2_kernel<<<(N_NODES + 255) / 256, 256>>>(out);
}

// round 12
// speedup vs baseline: 1.1542x; 1.0087x over previous
#include <cuda_runtime.h>
#include <cuda_fp16.h>
#include <math.h>
#include <stdint.h>

#define N_NODES 50000
#define N_EDGES 800000
#define D_IN    256
#define D_HID   128
#define D_ENC   64
#define MAXDEG  96
#define GEMM_BLOCKS ((N_NODES + 127) / 128)          // 391
#define DINV_BLOCKS 25                               // 25*256*8 >= 50000

// ---------------- scratch (static device globals; no allocations) ----------
__device__ int            d_counts[N_NODES];
__device__ float          d_dinv[N_NODES];
__device__ unsigned short d_ell[(size_t)N_NODES * MAXDEG]; // adjacency (u16 ids)
__device__ __half         d_g[(size_t)N_NODES * D_HID];    // dinv[r]*(x@W1)[r] fp16
__device__ float          d_td[N_NODES];                   // dinv[i] * (h1 . v)
__device__ float          d_v[D_HID];                      // W2 @ Wfc
__device__ float          d_s;                             // b2 . Wfc + bfc
__device__ float          d_W1t[D_HID * D_IN];             // W1 transposed [n][k]

__device__ __forceinline__ int clamp_node(int v) {
    return (v >= 0 && v < N_NODES) ? v : 0;
}

__device__ __forceinline__ uint32_t pack_bf16(float lo, float hi) {
    uint32_t r;
    asm("cvt.rn.bf16x2.f32 %0, %1, %2;" : "=r"(r) : "f"(hi), "f"(lo));
    return r;
}

// ---------------- single-pass ELL build (count + place) ---------------------
__global__ void fill_ell_kernel(const int* __restrict__ row,
                                const int* __restrict__ col) {
    int e = (blockIdx.x * blockDim.x + threadIdx.x) * 4;
    if (e + 3 < N_EDGES) {
        int4 c = *reinterpret_cast<const int4*>(col + e);
        int4 r = *reinterpret_cast<const int4*>(row + e);
        int c0 = clamp_node(c.x), c1 = clamp_node(c.y);
        int c2 = clamp_node(c.z), c3 = clamp_node(c.w);
        int p0 = atomicAdd(&d_counts[c0], 1);
        int p1 = atomicAdd(&d_counts[c1], 1);
        int p2 = atomicAdd(&d_counts[c2], 1);
        int p3 = atomicAdd(&d_counts[c3], 1);
        if (p0 < MAXDEG) d_ell[(size_t)c0 * MAXDEG + p0] = (unsigned short)clamp_node(r.x);
        if (p1 < MAXDEG) d_ell[(size_t)c1 * MAXDEG + p1] = (unsigned short)clamp_node(r.y);
        if (p2 < MAXDEG) d_ell[(size_t)c2 * MAXDEG + p2] = (unsigned short)clamp_node(r.z);
        if (p3 < MAXDEG) d_ell[(size_t)c3 * MAXDEG + p3] = (unsigned short)clamp_node(r.w);
    } else {
        for (int k = e; k < N_EDGES; k++) {
            int cc = clamp_node(col[k]);
            int p = atomicAdd(&d_counts[cc], 1);
            if (p < MAXDEG) d_ell[(size_t)cc * MAXDEG + p] = (unsigned short)clamp_node(row[k]);
        }
    }
}

// ---------------- weight prep: transpose W1 (32 blocks) + v,s (1 block) -----
__global__ void prep_weights_kernel(const float* __restrict__ W1,
                                    const float* __restrict__ W2,
                                    const float* __restrict__ b2,
                                    const float* __restrict__ Wfc,
                                    const float* __restrict__ bfc) {
    if (blockIdx.x < 32) {
        __shared__ float tt[32][33];
        int b = blockIdx.x;
        int bx = b & 7;
        int by = b >> 3;
        int x0 = bx * 32, y0 = by * 32;
        int tx = threadIdx.x & 31, ty = threadIdx.x >> 5;
        #pragma unroll
        for (int i = 0; i < 32; i += 8)
            tt[ty + i][tx] = W1[(size_t)(x0 + ty + i) * D_HID + y0 + tx];
        __syncthreads();
        #pragma unroll
        for (int i = 0; i < 32; i += 8)
            d_W1t[(size_t)(y0 + ty + i) * D_IN + x0 + tx] = tt[tx][ty + i];
    } else {
        __shared__ float red[D_ENC];
        int j = threadIdx.x;
        if (j < D_HID) {
            float acc = 0.f;
            #pragma unroll 8
            for (int k = 0; k < D_ENC; k++)
                acc = fmaf(W2[j * D_ENC + k], Wfc[k], acc);
            d_v[j] = acc;
        }
        if (j < D_ENC) red[j] = b2[j] * Wfc[j];
        __syncthreads();
        if (j == 0) {
            float s = bfc[0];
            for (int k = 0; k < D_ENC; k++) s += red[k];
            d_s = s;
        }
    }
}

// ---------------- GEMM1 (bf16 m16n8k16 mma); epilogue scales by dinv -> fp16
__global__ __launch_bounds__(256) void gemm1_mma_kernel(const float* __restrict__ x) {
    if (blockIdx.x >= GEMM_BLOCKS) {
        int base = ((blockIdx.x - GEMM_BLOCKS) * 256 + threadIdx.x) * 8;
        #pragma unroll
        for (int i = 0; i < 8; i++) {
            int idx = base + i;
            if (idx < N_NODES)
                d_dinv[idx] = rsqrtf((float)(d_counts[idx] + 1));  // deg = cnt+1
        }
        return;
    }

    __shared__ uint32_t As[128][20];
    __shared__ uint32_t Bs[128][20];

    int tid  = threadIdx.x;
    int warp = tid >> 5;
    int lane = tid & 31;
    int g  = lane >> 2;
    int tg = lane & 3;
    int rowBase = blockIdx.x * 128;

    float acc[16][4];
    #pragma unroll
    for (int nt = 0; nt < 16; nt++)
        #pragma unroll
        for (int i = 0; i < 4; i++) acc[nt][i] = 0.f;

    int lr = tid >> 1;
    int h  = tid & 1;
    int gr = rowBase + lr;
    bool valid = gr < N_NODES;
    const float4* pA = reinterpret_cast<const float4*>(
        x + (size_t)(valid ? gr : 0) * D_IN + h * 16);
    const float4* pB = reinterpret_cast<const float4*>(
        d_W1t + (size_t)lr * D_IN + h * 16);

    float4 ra[4], rb[4];
    #pragma unroll
    for (int i = 0; i < 4; i++) {
        ra[i] = valid ? pA[i] : make_float4(0.f, 0.f, 0.f, 0.f);
        rb[i] = pB[i];
    }
    #pragma unroll
    for (int i = 0; i < 4; i++) {
        As[lr][h * 8 + i * 2    ] = pack_bf16(ra[i].x, ra[i].y);
        As[lr][h * 8 + i * 2 + 1] = pack_bf16(ra[i].z, ra[i].w);
        Bs[lr][h * 8 + i * 2    ] = pack_bf16(rb[i].x, rb[i].y);
        Bs[lr][h * 8 + i * 2 + 1] = pack_bf16(rb[i].z, rb[i].w);
    }
    __syncthreads();

    #pragma unroll
    for (int c = 0; c < 8; c++) {
        if (c < 7) {
            #pragma unroll
            for (int i = 0; i < 4; i++) {
                ra[i] = valid ? pA[(c + 1) * 8 + i] : make_float4(0.f, 0.f, 0.f, 0.f);
                rb[i] = pB[(c + 1) * 8 + i];
            }
        }
        #pragma unroll
        for (int kk = 0; kk < 2; kk++) {
            uint32_t a0 = As[warp * 16 + g    ][kk * 8 + tg    ];
            uint32_t a1 = As[warp * 16 + g + 8][kk * 8 + tg    ];
            uint32_t a2 = As[warp * 16 + g    ][kk * 8 + 4 + tg];
            uint32_t a3 = As[warp * 16 + g + 8][kk * 8 + 4 + tg];
            #pragma unroll
            for (int nt = 0; nt < 16; nt++) {
                uint32_t b0 = Bs[nt * 8 + g][kk * 8 + tg    ];
                uint32_t b1 = Bs[nt * 8 + g][kk * 8 + 4 + tg];
                asm volatile(
                    "mma.sync.aligned.m16n8k16.row.col.f32.bf16.bf16.f32 "
                    "{%0,%1,%2,%3}, {%4,%5,%6,%7}, {%8,%9}, {%0,%1,%2,%3};"
                    : "+f"(acc[nt][0]), "+f"(acc[nt][1]),
                      "+f"(acc[nt][2]), "+f"(acc[nt][3])
                    : "r"(a0), "r"(a1), "r"(a2), "r"(a3), "r"(b0), "r"(b1));
            }
        }
        if (c < 7) {
            __syncthreads();
            #pragma unroll
            for (int i = 0; i < 4; i++) {
                As[lr][h * 8 + i * 2    ] = pack_bf16(ra[i].x, ra[i].y);
                As[lr][h * 8 + i * 2 + 1] = pack_bf16(ra[i].z, ra[i].w);
                Bs[lr][h * 8 + i * 2    ] = pack_bf16(rb[i].x, rb[i].y);
                Bs[lr][h * 8 + i * 2 + 1] = pack_bf16(rb[i].z, rb[i].w);
            }
            __syncthreads();
        }
    }

    int r0 = rowBase + warp * 16 + g;
    int r1 = r0 + 8;
    float di0 = (r0 < N_NODES) ? rsqrtf((float)(d_counts[r0] + 1)) : 0.f;
    float di1 = (r1 < N_NODES) ? rsqrtf((float)(d_counts[r1] + 1)) : 0.f;
    __half2* g2 = reinterpret_cast<__half2*>(d_g);
    #pragma unroll
    for (int nt = 0; nt < 16; nt++) {
        int hh = nt * 4 + tg;
        if (r0 < N_NODES)
            g2[(size_t)r0 * 64 + hh] =
                __floats2half2_rn(di0 * acc[nt][0], di0 * acc[nt][1]);
        if (r1 < N_NODES)
            g2[(size_t)r1 * 64 + hh] =
                __floats2half2_rn(di1 * acc[nt][2], di1 * acc[nt][3]);
    }
}

// ---------------- layer-1 aggregation: u16 indices + depth-1 HADD2 ----------
__global__ __launch_bounds__(256) void agg1_kernel(const float* __restrict__ b1) {
    int gwarp = (blockIdx.x * blockDim.x + threadIdx.x) >> 5;
    int lane  = threadIdx.x & 31;
    if (gwarp >= N_NODES) return;
    int node  = gwarp;
    int cnt   = d_counts[node];
    if (cnt > MAXDEG) cnt = MAXDEG;
    const unsigned short* adj = d_ell + (size_t)node * MAXDEG;
    float di  = d_dinv[node];
    const uint2* g4 = reinterpret_cast<const uint2*>(d_g);

    float4 acc = make_float4(0.f, 0.f, 0.f, 0.f);
    int j = 0;
    for (; j + 4 <= cnt; j += 4) {
        ushort4 ss = *reinterpret_cast<const ushort4*>(adj + j);  // 4 ids, 1 LDG
        uint2 u0 = g4[(size_t)ss.x * 32 + lane];
        uint2 u1 = g4[(size_t)ss.y * 32 + lane];
        uint2 u2 = g4[(size_t)ss.z * 32 + lane];
        uint2 u3 = g4[(size_t)ss.w * 32 + lane];
        // depth-1 fp16 pairwise sums, then fp32 accumulate
        __half2 h01a = __hadd2(*reinterpret_cast<__half2*>(&u0.x),
                               *reinterpret_cast<__half2*>(&u1.x));
        __half2 h01b = __hadd2(*reinterpret_cast<__half2*>(&u0.y),
                               *reinterpret_cast<__half2*>(&u1.y));
        __half2 h23a = __hadd2(*reinterpret_cast<__half2*>(&u2.x),
                               *reinterpret_cast<__half2*>(&u3.x));
        __half2 h23b = __hadd2(*reinterpret_cast<__half2*>(&u2.y),
                               *reinterpret_cast<__half2*>(&u3.y));
        float2 f0 = __half22float2(h01a);
        float2 f1 = __half22float2(h01b);
        float2 f2 = __half22float2(h23a);
        float2 f3 = __half22float2(h23b);
        acc.x += f0.x + f2.x; acc.y += f0.y + f2.y;
        acc.z += f1.x + f3.x; acc.w += f1.y + f3.y;
    }
    for (; j < cnt; j++) {
        int s0 = adj[j];
        uint2 u0 = g4[(size_t)s0 * 32 + lane];
        float2 a0 = __half22float2(*reinterpret_cast<__half2*>(&u0.x));
        float2 a1 = __half22float2(*reinterpret_cast<__half2*>(&u0.y));
        acc.x += a0.x; acc.y += a0.y;
        acc.z += a1.x; acc.w += a1.y;
    }
    {   // self loop (row pre-scaled by dinv[node])
        uint2 u0 = g4[(size_t)node * 32 + lane];
        float2 a0 = __half22float2(*reinterpret_cast<__half2*>(&u0.x));
        float2 a1 = __half22float2(*reinterpret_cast<__half2*>(&u0.y));
        acc.x += a0.x; acc.y += a0.y;
        acc.z += a1.x; acc.w += a1.y;
    }
    float4 bb = reinterpret_cast<const float4*>(b1)[lane];
    float4 vv = reinterpret_cast<const float4*>(d_v)[lane];
    float h0 = fmaxf(fmaf(acc.x, di, bb.x), 0.f);
    float h1 = fmaxf(fmaf(acc.y, di, bb.y), 0.f);
    float h2 = fmaxf(fmaf(acc.z, di, bb.z), 0.f);
    float h3 = fmaxf(fmaf(acc.w, di, bb.w), 0.f);
    float p = h0 * vv.x + h1 * vv.y + h2 * vv.z + h3 * vv.w;
    #pragma unroll
    for (int off = 16; off > 0; off >>= 1)
        p += __shfl_down_sync(0xFFFFFFFFu, p, off);
    if (lane == 0) d_td[node] = di * p;
}

// ---------------- layer-2 (collapsed, scalar) + sigmoid ---------------------
__global__ void agg2_kernel(float* __restrict__ out) {
    int i = blockIdx.x * blockDim.x + threadIdx.x;
    if (i >= N_NODES) return;
    int cnt = d_counts[i];
    if (cnt > MAXDEG) cnt = MAXDEG;
    const unsigned short* adj = d_ell + (size_t)i * MAXDEG;
    float acc = 0.f;
    int j = 0;
    for (; j + 4 <= cnt; j += 4) {
        ushort4 ss = *reinterpret_cast<const ushort4*>(adj + j);
        acc += d_td[ss.x] + d_td[ss.y] + d_td[ss.z] + d_td[ss.w];
    }
    for (; j < cnt; j++) acc += d_td[adj[j]];
    float di = d_dinv[i];
    float u = di * (acc + d_td[i]) + d_s;
    out[i] = 1.f / (1.f + expf(-u));
}

// ---------------- launcher ---------------------------------------------------
extern "C" void kernel_launch(void* const* d_in, const int* in_sizes, int n_in,
                              void* d_out, int out_size) {
    const float* x   = (const float*)d_in[0];
    const int*   ei  = (const int*)d_in[1];
    const float* W1  = (const float*)d_in[2];
    const float* b1  = (const float*)d_in[3];
    const float* W2  = (const float*)d_in[4];
    const float* b2  = (const float*)d_in[5];
    const float* Wfc = (const float*)d_in[6];
    const float* bfc = (const float*)d_in[7];
    float* out = (float*)d_out;

    const int* row = ei;            // sources
    const int* col = ei + N_EDGES;  // targets

    void* counts_ptr = nullptr;
    cudaGetSymbolAddress(&counts_ptr, d_counts);
    cudaMemsetAsync(counts_ptr, 0, N_NODES * sizeof(int));

    prep_weights_kernel<<<33, 256>>>(W1, W2, b2, Wfc, bfc);
    fill_ell_kernel<<<(N_EDGES / 4 + 255) / 256, 256>>>(row, col);
    gemm1_mma_kernel<<<GEMM_BLOCKS + DINV_BLOCKS, 256>>>(x);
    agg1_kernel<<<(N_NODES + 7) / 8, 256>>>(b1);
    agg2_kernel<<<(N_NODES + 255) / 256, 256>>>(out);
}

// round 13
// speedup vs baseline: 1.1778x; 1.0205x over previous
#include <cuda_runtime.h>
#include <cuda_fp16.h>
#include <math.h>
#include <stdint.h>

#define N_NODES 50000
#define N_EDGES 800000
#define D_IN    256
#define D_HID   128
#define D_ENC   64
#define MAXDEG  96
#define GEMM_BLOCKS ((N_NODES + 127) / 128)          // 391

// ---------------- scratch (static device globals; no allocations) ----------
__device__ int            d_counts[N_NODES];
__device__ float          d_dinv[N_NODES];
__device__ unsigned short d_ell[(size_t)N_NODES * MAXDEG]; // adjacency (u16 ids)
__device__ __half         d_g[(size_t)N_NODES * D_HID];    // (x@W1), then scaled
__device__ float          d_td[N_NODES];                   // dinv[i] * (h1 . v)
__device__ float          d_v[D_HID];                      // W2 @ Wfc
__device__ float          d_s;                             // b2 . Wfc + bfc
__device__ float          d_W1t[D_HID * D_IN];             // W1 transposed [n][k]

__device__ __forceinline__ int clamp_node(int v) {
    return (v >= 0 && v < N_NODES) ? v : 0;
}

__device__ __forceinline__ uint32_t pack_bf16(float lo, float hi) {
    uint32_t r;
    asm("cvt.rn.bf16x2.f32 %0, %1, %2;" : "=r"(r) : "f"(hi), "f"(lo));
    return r;
}

// ---------------- single-pass ELL build (count + place) ---------------------
__global__ void fill_ell_kernel(const int* __restrict__ row,
                                const int* __restrict__ col) {
    int e = (blockIdx.x * blockDim.x + threadIdx.x) * 4;
    if (e + 3 < N_EDGES) {
        int4 c = *reinterpret_cast<const int4*>(col + e);
        int4 r = *reinterpret_cast<const int4*>(row + e);
        int c0 = clamp_node(c.x), c1 = clamp_node(c.y);
        int c2 = clamp_node(c.z), c3 = clamp_node(c.w);
        int p0 = atomicAdd(&d_counts[c0], 1);
        int p1 = atomicAdd(&d_counts[c1], 1);
        int p2 = atomicAdd(&d_counts[c2], 1);
        int p3 = atomicAdd(&d_counts[c3], 1);
        if (p0 < MAXDEG) d_ell[(size_t)c0 * MAXDEG + p0] = (unsigned short)clamp_node(r.x);
        if (p1 < MAXDEG) d_ell[(size_t)c1 * MAXDEG + p1] = (unsigned short)clamp_node(r.y);
        if (p2 < MAXDEG) d_ell[(size_t)c2 * MAXDEG + p2] = (unsigned short)clamp_node(r.z);
        if (p3 < MAXDEG) d_ell[(size_t)c3 * MAXDEG + p3] = (unsigned short)clamp_node(r.w);
    } else {
        for (int k = e; k < N_EDGES; k++) {
            int cc = clamp_node(col[k]);
            int p = atomicAdd(&d_counts[cc], 1);
            if (p < MAXDEG) d_ell[(size_t)cc * MAXDEG + p] = (unsigned short)clamp_node(row[k]);
        }
    }
}

// ---------------- weight prep: transpose W1 (32 blocks) + v,s (1 block) -----
__global__ void prep_weights_kernel(const float* __restrict__ W1,
                                    const float* __restrict__ W2,
                                    const float* __restrict__ b2,
                                    const float* __restrict__ Wfc,
                                    const float* __restrict__ bfc) {
    if (blockIdx.x < 32) {
        __shared__ float tt[32][33];
        int b = blockIdx.x;
        int bx = b & 7;
        int by = b >> 3;
        int x0 = bx * 32, y0 = by * 32;
        int tx = threadIdx.x & 31, ty = threadIdx.x >> 5;
        #pragma unroll
        for (int i = 0; i < 32; i += 8)
            tt[ty + i][tx] = W1[(size_t)(x0 + ty + i) * D_HID + y0 + tx];
        __syncthreads();
        #pragma unroll
        for (int i = 0; i < 32; i += 8)
            d_W1t[(size_t)(y0 + ty + i) * D_IN + x0 + tx] = tt[tx][ty + i];
    } else {
        __shared__ float red[D_ENC];
        int j = threadIdx.x;
        if (j < D_HID) {
            float acc = 0.f;
            #pragma unroll 8
            for (int k = 0; k < D_ENC; k++)
                acc = fmaf(W2[j * D_ENC + k], Wfc[k], acc);
            d_v[j] = acc;
        }
        if (j < D_ENC) red[j] = b2[j] * Wfc[j];
        __syncthreads();
        if (j == 0) {
            float s = bfc[0];
            for (int k = 0; k < D_ENC; k++) s += red[k];
            d_s = s;
        }
    }
}

// ---------------- GEMM1 (bf16 m16n8k16 mma); UNSCALED fp16 output -----------
__global__ __launch_bounds__(256) void gemm1_mma_kernel(const float* __restrict__ x) {
    __shared__ uint32_t As[128][20];
    __shared__ uint32_t Bs[128][20];

    int tid  = threadIdx.x;
    int warp = tid >> 5;
    int lane = tid & 31;
    int g  = lane >> 2;
    int tg = lane & 3;
    int rowBase = blockIdx.x * 128;

    float acc[16][4];
    #pragma unroll
    for (int nt = 0; nt < 16; nt++)
        #pragma unroll
        for (int i = 0; i < 4; i++) acc[nt][i] = 0.f;

    int lr = tid >> 1;
    int h  = tid & 1;
    int gr = rowBase + lr;
    bool valid = gr < N_NODES;
    const float4* pA = reinterpret_cast<const float4*>(
        x + (size_t)(valid ? gr : 0) * D_IN + h * 16);
    const float4* pB = reinterpret_cast<const float4*>(
        d_W1t + (size_t)lr * D_IN + h * 16);

    float4 ra[4], rb[4];
    #pragma unroll
    for (int i = 0; i < 4; i++) {
        ra[i] = valid ? pA[i] : make_float4(0.f, 0.f, 0.f, 0.f);
        rb[i] = pB[i];
    }
    #pragma unroll
    for (int i = 0; i < 4; i++) {
        As[lr][h * 8 + i * 2    ] = pack_bf16(ra[i].x, ra[i].y);
        As[lr][h * 8 + i * 2 + 1] = pack_bf16(ra[i].z, ra[i].w);
        Bs[lr][h * 8 + i * 2    ] = pack_bf16(rb[i].x, rb[i].y);
        Bs[lr][h * 8 + i * 2 + 1] = pack_bf16(rb[i].z, rb[i].w);
    }
    __syncthreads();

    #pragma unroll
    for (int c = 0; c < 8; c++) {
        if (c < 7) {
            #pragma unroll
            for (int i = 0; i < 4; i++) {
                ra[i] = valid ? pA[(c + 1) * 8 + i] : make_float4(0.f, 0.f, 0.f, 0.f);
                rb[i] = pB[(c + 1) * 8 + i];
            }
        }
        #pragma unroll
        for (int kk = 0; kk < 2; kk++) {
            uint32_t a0 = As[warp * 16 + g    ][kk * 8 + tg    ];
            uint32_t a1 = As[warp * 16 + g + 8][kk * 8 + tg    ];
            uint32_t a2 = As[warp * 16 + g    ][kk * 8 + 4 + tg];
            uint32_t a3 = As[warp * 16 + g + 8][kk * 8 + 4 + tg];
            #pragma unroll
            for (int nt = 0; nt < 16; nt++) {
                uint32_t b0 = Bs[nt * 8 + g][kk * 8 + tg    ];
                uint32_t b1 = Bs[nt * 8 + g][kk * 8 + 4 + tg];
                asm volatile(
                    "mma.sync.aligned.m16n8k16.row.col.f32.bf16.bf16.f32 "
                    "{%0,%1,%2,%3}, {%4,%5,%6,%7}, {%8,%9}, {%0,%1,%2,%3};"
                    : "+f"(acc[nt][0]), "+f"(acc[nt][1]),
                      "+f"(acc[nt][2]), "+f"(acc[nt][3])
                    : "r"(a0), "r"(a1), "r"(a2), "r"(a3), "r"(b0), "r"(b1));
            }
        }
        if (c < 7) {
            __syncthreads();
            #pragma unroll
            for (int i = 0; i < 4; i++) {
                As[lr][h * 8 + i * 2    ] = pack_bf16(ra[i].x, ra[i].y);
                As[lr][h * 8 + i * 2 + 1] = pack_bf16(ra[i].z, ra[i].w);
                Bs[lr][h * 8 + i * 2    ] = pack_bf16(rb[i].x, rb[i].y);
                Bs[lr][h * 8 + i * 2 + 1] = pack_bf16(rb[i].z, rb[i].w);
            }
            __syncthreads();
        }
    }

    int r0 = rowBase + warp * 16 + g;
    int r1 = r0 + 8;
    __half2* g2 = reinterpret_cast<__half2*>(d_g);
    #pragma unroll
    for (int nt = 0; nt < 16; nt++) {
        int hh = nt * 4 + tg;
        if (r0 < N_NODES)
            g2[(size_t)r0 * 64 + hh] = __floats2half2_rn(acc[nt][0], acc[nt][1]);
        if (r1 < N_NODES)
            g2[(size_t)r1 * 64 + hh] = __floats2half2_rn(acc[nt][2], acc[nt][3]);
    }
}

// ---------------- scale g rows by dinv; emit d_dinv -------------------------
// one uint4 (8 halves) per thread; 16 uint4 per row
__global__ __launch_bounds__(256) void scale_g_kernel() {
    int idx = blockIdx.x * blockDim.x + threadIdx.x;   // uint4 index
    int row = idx >> 4;
    if (row >= N_NODES) return;
    float di = rsqrtf((float)(d_counts[row] + 1));     // deg = cnt + 1
    if ((idx & 15) == 0) d_dinv[row] = di;
    uint4* g16 = reinterpret_cast<uint4*>(d_g);
    uint4 u = g16[idx];
    __half2* hp = reinterpret_cast<__half2*>(&u);
    #pragma unroll
    for (int i = 0; i < 4; i++) {
        float2 f = __half22float2(hp[i]);
        hp[i] = __floats2half2_rn(di * f.x, di * f.y);
    }
    g16[idx] = u;
}

// ---------------- layer-1 aggregation: u16 indices + depth-1 HADD2 ----------
__global__ __launch_bounds__(256) void agg1_kernel(const float* __restrict__ b1) {
    int gwarp = (blockIdx.x * blockDim.x + threadIdx.x) >> 5;
    int lane  = threadIdx.x & 31;
    if (gwarp >= N_NODES) return;
    int node  = gwarp;
    int cnt   = d_counts[node];
    if (cnt > MAXDEG) cnt = MAXDEG;
    const unsigned short* adj = d_ell + (size_t)node * MAXDEG;
    float di  = d_dinv[node];
    const uint2* g4 = reinterpret_cast<const uint2*>(d_g);

    float4 acc = make_float4(0.f, 0.f, 0.f, 0.f);
    int j = 0;
    for (; j + 4 <= cnt; j += 4) {
        ushort4 ss = *reinterpret_cast<const ushort4*>(adj + j);
        uint2 u0 = g4[(size_t)ss.x * 32 + lane];
        uint2 u1 = g4[(size_t)ss.y * 32 + lane];
        uint2 u2 = g4[(size_t)ss.z * 32 + lane];
        uint2 u3 = g4[(size_t)ss.w * 32 + lane];
        __half2 h01a = __hadd2(*reinterpret_cast<__half2*>(&u0.x),
                               *reinterpret_cast<__half2*>(&u1.x));
        __half2 h01b = __hadd2(*reinterpret_cast<__half2*>(&u0.y),
                               *reinterpret_cast<__half2*>(&u1.y));
        __half2 h23a = __hadd2(*reinterpret_cast<__half2*>(&u2.x),
                               *reinterpret_cast<__half2*>(&u3.x));
        __half2 h23b = __hadd2(*reinterpret_cast<__half2*>(&u2.y),
                               *reinterpret_cast<__half2*>(&u3.y));
        float2 f0 = __half22float2(h01a);
        float2 f1 = __half22float2(h01b);
        float2 f2 = __half22float2(h23a);
        float2 f3 = __half22float2(h23b);
        acc.x += f0.x + f2.x; acc.y += f0.y + f2.y;
        acc.z += f1.x + f3.x; acc.w += f1.y + f3.y;
    }
    for (; j < cnt; j++) {
        int s0 = adj[j];
        uint2 u0 = g4[(size_t)s0 * 32 + lane];
        float2 a0 = __half22float2(*reinterpret_cast<__half2*>(&u0.x));
        float2 a1 = __half22float2(*reinterpret_cast<__half2*>(&u0.y));
        acc.x += a0.x; acc.y += a0.y;
        acc.z += a1.x; acc.w += a1.y;
    }
    {   // self loop (row pre-scaled by dinv[node])
        uint2 u0 = g4[(size_t)node * 32 + lane];
        float2 a0 = __half22float2(*reinterpret_cast<__half2*>(&u0.x));
        float2 a1 = __half22float2(*reinterpret_cast<__half2*>(&u0.y));
        acc.x += a0.x; acc.y += a0.y;
        acc.z += a1.x; acc.w += a1.y;
    }
    float4 bb = reinterpret_cast<const float4*>(b1)[lane];
    float4 vv = reinterpret_cast<const float4*>(d_v)[lane];
    float h0 = fmaxf(fmaf(acc.x, di, bb.x), 0.f);
    float h1 = fmaxf(fmaf(acc.y, di, bb.y), 0.f);
    float h2 = fmaxf(fmaf(acc.z, di, bb.z), 0.f);
    float h3 = fmaxf(fmaf(acc.w, di, bb.w), 0.f);
    float p = h0 * vv.x + h1 * vv.y + h2 * vv.z + h3 * vv.w;
    #pragma unroll
    for (int off = 16; off > 0; off >>= 1)
        p += __shfl_down_sync(0xFFFFFFFFu, p, off);
    if (lane == 0) d_td[node] = di * p;
}

// ---------------- layer-2 (collapsed, scalar) + sigmoid ---------------------
__global__ void agg2_kernel(float* __restrict__ out) {
    int i = blockIdx.x * blockDim.x + threadIdx.x;
    if (i >= N_NODES) return;
    int cnt = d_counts[i];
    if (cnt > MAXDEG) cnt = MAXDEG;
    const unsigned short* adj = d_ell + (size_t)i * MAXDEG;
    float acc = 0.f;
    int j = 0;
    for (; j + 4 <= cnt; j += 4) {
        ushort4 ss = *reinterpret_cast<const ushort4*>(adj + j);
        acc += d_td[ss.x] + d_td[ss.y] + d_td[ss.z] + d_td[ss.w];
    }
    for (; j < cnt; j++) acc += d_td[adj[j]];
    float di = d_dinv[i];
    float u = di * (acc + d_td[i]) + d_s;
    out[i] = 1.f / (1.f + expf(-u));
}

// ---------------- launcher with fork/join overlap ---------------------------
extern "C" void kernel_launch(void* const* d_in, const int* in_sizes, int n_in,
                              void* d_out, int out_size) {
    const float* x   = (const float*)d_in[0];
    const int*   ei  = (const int*)d_in[1];
    const float* W1  = (const float*)d_in[2];
    const float* b1  = (const float*)d_in[3];
    const float* W2  = (const float*)d_in[4];
    const float* b2  = (const float*)d_in[5];
    const float* Wfc = (const float*)d_in[6];
    const float* bfc = (const float*)d_in[7];
    float* out = (float*)d_out;

    const int* row = ei;            // sources
    const int* col = ei + N_EDGES;  // targets

    // created once on the (uncaptured) correctness call; reused during capture
    static cudaStream_t side = nullptr;
    static cudaEvent_t  evFork = nullptr, evJoin = nullptr;
    if (side == nullptr) {
        cudaStreamCreateWithFlags(&side, cudaStreamNonBlocking);
        cudaEventCreateWithFlags(&evFork, cudaEventDisableTiming);
        cudaEventCreateWithFlags(&evJoin, cudaEventDisableTiming);
    }

    void* counts_ptr = nullptr;
    cudaGetSymbolAddress(&counts_ptr, d_counts);

    // fork: side stream does weight prep + GEMM (independent of edges)
    cudaEventRecord(evFork, 0);
    cudaStreamWaitEvent(side, evFork, 0);
    prep_weights_kernel<<<33, 256, 0, side>>>(W1, W2, b2, Wfc, bfc);
    gemm1_mma_kernel<<<GEMM_BLOCKS, 256, 0, side>>>(x);

    // main stream: counts reset + ELL build
    cudaMemsetAsync(counts_ptr, 0, N_NODES * sizeof(int), 0);
    fill_ell_kernel<<<(N_EDGES / 4 + 255) / 256, 256, 0, 0>>>(row, col);

    // join
    cudaEventRecord(evJoin, side);
    cudaStreamWaitEvent(0, evJoin, 0);

    scale_g_kernel<<<(N_NODES * 16 + 255) / 256, 256, 0, 0>>>();
    agg1_kernel<<<(N_NODES + 7) / 8, 256, 0, 0>>>(b1);
    agg2_kernel<<<(N_NODES + 255) / 256, 256, 0, 0>>>(out);
}